// round 13
// baseline (speedup 1.0000x reference)
#include <cuda_runtime.h>
#include <cuda_fp16.h>
#include <math.h>
#include <stdint.h>

#define NN 10000
#define EE 160000
#define ETOT 170000   // EE + NN self loops
#define HH 8
#define CC 128
#define DD 1024
#define WSZ (DD * CC) // 131072 elements per weight matrix

#define GROUP 16      // dst nodes per aggregate block (NN % 16 == 0)
#define CHUNK 16      // edges per MMA chunk
#define HSTR 1032     // smem H row stride in halves (1024 + 8 pad -> conflict-free ldmatrix)
#define PSTR 24       // smem P row stride in halves (16 + 8 pad -> conflict-free A-frag LDS)
#define PBUF (HH * GROUP * PSTR)   // 3072 halves per P buffer

// ---------------- scratch (static device memory; no allocations) ----------------
__device__ __half g_h16[NN * DD];     // fp16 per-layer h (gather + scores source)
__device__ __half g_agg16[NN * DD];   // fp16 aggregate output (feeds small GEMM)
__device__ __half g_feat16[NN * CC];  // fp16 feat (small GEMM out, big GEMM in)
__device__ float g_ssrc[NN * HH];
__device__ float g_sdst[NN * HH];
__device__ int   g_cnt[NN];           // BSS-zeroed; re-zeroed by k_scan each call
__device__ int   g_row[NN + 1];
__device__ int   g_cur[NN];
__device__ int   g_esrc[ETOT];        // src node per CSR position
__device__ int   g_edst[ETOT];        // dst node per CSR position
__device__ __half g_wt[5 * WSZ];      // transposed fp16 weights [Nc,K]

__device__ __forceinline__ float gelu_exact(float x) {
    return x * normcdff(x);   // jax.nn.gelu(approximate=False)
}
__device__ __forceinline__ int edge_src(const int* ei, int e) {
    return (e < EE) ? ei[e] : (e - EE);
}
__device__ __forceinline__ int edge_dst(const int* ei, int e) {
    return (e < EE) ? ei[EE + e] : (e - EE);
}

// ---------------- fused: weight convert+transpose AND edge counting ----------------
__global__ void k_cvt_count(const float* __restrict__ w0, const float* __restrict__ w1_,
                            const float* __restrict__ w2_, const float* __restrict__ w3_,
                            const float* __restrict__ w4_, const int* __restrict__ ei) {
    int idx = blockIdx.x * 256 + threadIdx.x;
    if (idx < 5 * WSZ) {
        int which = idx / WSZ, r = idx - which * WSZ;
        const float* W;
        int K, Nc;
        switch (which) {
            case 0: W = w0;  K = 1024; Nc = 128;  break;
            case 1: W = w1_; K = 128;  Nc = 1024; break;
            case 2: W = w2_; K = 1024; Nc = 128;  break;
            case 3: W = w3_; K = 128;  Nc = 1024; break;
            default: W = w4_; K = 1024; Nc = 128; break;
        }
        int k = r / Nc, n = r - k * Nc;
        g_wt[which * WSZ + n * K + k] = __float2half_rn(W[r]);
    }
    if (idx < ETOT) atomicAdd(&g_cnt[edge_dst(ei, idx)], 1);
}

__global__ void k_scan() {
    __shared__ int sh[1024];
    int t = threadIdx.x;
    int base = t * 10;
    int cnt[10];
    int s = 0;
#pragma unroll
    for (int i = 0; i < 10; i++) {
        int j = base + i;
        cnt[i] = (j < NN) ? g_cnt[j] : 0;
        s += cnt[i];
        if (j < NN) g_cnt[j] = 0;
    }
    sh[t] = s;
    __syncthreads();
    for (int off = 1; off < 1024; off <<= 1) {
        int v = (t >= off) ? sh[t - off] : 0;
        __syncthreads();
        sh[t] += v;
        __syncthreads();
    }
    int run = sh[t] - s;
    for (int i = 0; i < 10; i++) {
        int j = base + i;
        if (j < NN) { g_row[j] = run; g_cur[j] = run; run += cnt[i]; }
    }
    if (t == 1023) g_row[NN] = sh[1023];
}

// ---------------- fused: CSR fill (blocks 0..664) + layer-1 h/scores (blocks 665..) ----------------
__global__ void __launch_bounds__(256) k_fill_l1(const int* __restrict__ ei,
                                                 const float* __restrict__ x,
                                                 const float* __restrict__ w1,
                                                 const float* __restrict__ asrc,
                                                 const float* __restrict__ adst,
                                                 __half* __restrict__ h16) {
    if (blockIdx.x < 665) {
        int e = blockIdx.x * 256 + threadIdx.x;
        if (e < ETOT) {
            int d = edge_dst(ei, e);
            int pos = atomicAdd(&g_cur[d], 1);
            g_esrc[pos] = edge_src(ei, e);
            g_edst[pos] = d;
        }
        return;
    }
    int n = blockIdx.x - 665;
    int w = threadIdx.x >> 5, lane = threadIdx.x & 31;
    float4 xv = *(const float4*)(x + n * 4);
    int db = w * CC + lane * 4;
    float4 c0 = *(const float4*)(w1 + 0 * DD + db);
    float4 c1 = *(const float4*)(w1 + 1 * DD + db);
    float4 c2 = *(const float4*)(w1 + 2 * DD + db);
    float4 c3 = *(const float4*)(w1 + 3 * DD + db);
    float h0 = xv.x * c0.x + xv.y * c1.x + xv.z * c2.x + xv.w * c3.x;
    float h1 = xv.x * c0.y + xv.y * c1.y + xv.z * c2.y + xv.w * c3.y;
    float h2 = xv.x * c0.z + xv.y * c1.z + xv.z * c2.z + xv.w * c3.z;
    float h3 = xv.x * c0.w + xv.y * c1.w + xv.z * c2.w + xv.w * c3.w;
    __half2 p01 = __floats2half2_rn(h0, h1);
    __half2 p23 = __floats2half2_rn(h2, h3);
    uint2 packed = make_uint2(*(uint32_t*)&p01, *(uint32_t*)&p23);
    *(uint2*)(h16 + (size_t)n * DD + db) = packed;

    float4 a = *(const float4*)(asrc + db);
    float4 d = *(const float4*)(adst + db);
    float s1 = h0 * a.x + h1 * a.y + h2 * a.z + h3 * a.w;
    float s2 = h0 * d.x + h1 * d.y + h2 * d.z + h3 * d.w;
#pragma unroll
    for (int o = 16; o > 0; o >>= 1) {
        s1 += __shfl_xor_sync(0xffffffffu, s1, o);
        s2 += __shfl_xor_sync(0xffffffffu, s2, o);
    }
    if (lane == 0) {
        g_ssrc[n * HH + w] = s1;
        g_sdst[n * HH + w] = s2;
    }
}

// ---------------- MMA helpers ----------------
__device__ __forceinline__ void mma_f16(float* c, const uint32_t* a, const uint32_t* b) {
    asm volatile(
        "mma.sync.aligned.m16n8k16.row.col.f32.f16.f16.f32 "
        "{%0,%1,%2,%3}, {%4,%5,%6,%7}, {%8,%9}, {%0,%1,%2,%3};"
        : "+f"(c[0]), "+f"(c[1]), "+f"(c[2]), "+f"(c[3])
        : "r"(a[0]), "r"(a[1]), "r"(a[2]), "r"(a[3]), "r"(b[0]), "r"(b[1]));
}
__device__ __forceinline__ void ldmatrix_x2_trans(uint32_t& r0, uint32_t& r1, uint32_t addr) {
    asm volatile("ldmatrix.sync.aligned.m8n8.x2.trans.shared.b16 {%0,%1}, [%2];"
                 : "=r"(r0), "=r"(r1) : "r"(addr));
}

// ---------------- fp16 GEMM, double-buffered smem ----------------
template <int BM, bool GELU_A, bool ADD_BIAS, bool OUT_HALF, bool SCORES>
__global__ void __launch_bounds__(256) k_gemm(
    const __half* __restrict__ Ahg, const __half* __restrict__ Bg,
    const float* __restrict__ bias,
    const float* __restrict__ asrc, const float* __restrict__ adst,
    float* __restrict__ Cf, __half* __restrict__ Ch, int M, int K, int Nc) {
    constexpr int STR = 40;
    constexpr int WM = BM / 2;
    constexpr int MT = WM / 16;

    extern __shared__ __half dsm[];
    __half* AsB = dsm;
    __half* BsB = dsm + 2 * BM * STR;
    __shared__ float sa[128], sd[128];
    __shared__ float sSp[4][128], sDp[4][128];

    const int tid = threadIdx.x;
    const int wid = tid >> 5, lane = tid & 31;
    const int wm = wid & 1, wn = wid >> 1;
    const int gr = lane >> 2, tc = lane & 3;
    const int m0 = blockIdx.y * BM, n0 = blockIdx.x * 128;
    const int head = blockIdx.x;

    if (SCORES && tid < 128) {
        sa[tid] = asrc[head * 128 + tid];
        sd[tid] = adst[head * 128 + tid];
    }

    float acc[MT][4][4];
#pragma unroll
    for (int i = 0; i < MT; i++)
#pragma unroll
        for (int j = 0; j < 4; j++)
#pragma unroll
            for (int q = 0; q < 4; q++) acc[i][j][q] = 0.f;

    uint4 rAh128[2];
    uint2 rAh32;
    uint4 rB[2];
    const int ar128 = tid >> 1, aq128 = (tid & 1) * 2;
    const int ar32 = tid >> 3, aq32 = tid & 7;
    const int br_ = tid >> 1, bq_ = tid & 1;

    auto load_chunk = [&](int k0) {
        if (BM == 128) {
#pragma unroll
            for (int it = 0; it < 2; it++) {
                int q = aq128 + it;
                rAh128[it] = (m0 + ar128 < M)
                    ? *(const uint4*)(Ahg + (size_t)(m0 + ar128) * K + k0 + q * 8)
                    : make_uint4(0, 0, 0, 0);
            }
        } else {
            rAh32 = (m0 + ar32 < M)
                ? *(const uint2*)(Ahg + (size_t)(m0 + ar32) * K + k0 + aq32 * 4)
                : make_uint2(0, 0);
        }
#pragma unroll
        for (int it = 0; it < 2; it++) {
            int q = bq_ + it * 2;
            rB[it] = *(const uint4*)(Bg + (size_t)(n0 + br_) * K + k0 + q * 8);
        }
    };
    auto store_chunk = [&](int stage) {
        __half* As = AsB + stage * BM * STR;
        __half* Bs = BsB + stage * 128 * STR;
        if (BM == 128) {
#pragma unroll
            for (int it = 0; it < 2; it++) {
                int q = aq128 + it;
                *(uint4*)&As[ar128 * STR + q * 8] = rAh128[it];
            }
        } else {
            uint2 v = rAh32;
            if (GELU_A) {
                __half2 x01 = *(__half2*)&v.x;
                __half2 x23 = *(__half2*)&v.y;
                float2 f01 = __half22float2(x01);
                float2 f23 = __half22float2(x23);
                __half2 g01 = __floats2half2_rn(gelu_exact(f01.x), gelu_exact(f01.y));
                __half2 g23 = __floats2half2_rn(gelu_exact(f23.x), gelu_exact(f23.y));
                v = make_uint2(*(uint32_t*)&g01, *(uint32_t*)&g23);
            }
            *(uint2*)&As[ar32 * STR + aq32 * 4] = v;
        }
#pragma unroll
        for (int it = 0; it < 2; it++) {
            int q = bq_ + it * 2;
            *(uint4*)&Bs[br_ * STR + q * 8] = rB[it];
        }
    };

    const int nchunks = K >> 5;
    load_chunk(0);
    store_chunk(0);
    __syncthreads();

    for (int c = 0; c < nchunks; c++) {
        int b = c & 1;
        if (c + 1 < nchunks) load_chunk((c + 1) << 5);

        const __half* As = AsB + b * BM * STR;
        const __half* Bs = BsB + b * 128 * STR;
#pragma unroll
        for (int ks = 0; ks < 32; ks += 16) {
            uint32_t af[MT][4], bf[4][2];
#pragma unroll
            for (int i = 0; i < MT; i++) {
                int row = wm * WM + i * 16 + gr;
                int o = row * STR + ks + tc * 2;
                af[i][0] = *(const uint32_t*)&As[o];
                af[i][1] = *(const uint32_t*)&As[o + 8 * STR];
                af[i][2] = *(const uint32_t*)&As[o + 8];
                af[i][3] = *(const uint32_t*)&As[o + 8 * STR + 8];
            }
#pragma unroll
            for (int j = 0; j < 4; j++) {
                int nrow = wn * 32 + j * 8 + gr;
                int o = nrow * STR + ks + tc * 2;
                bf[j][0] = *(const uint32_t*)&Bs[o];
                bf[j][1] = *(const uint32_t*)&Bs[o + 8];
            }
#pragma unroll
            for (int i = 0; i < MT; i++)
#pragma unroll
                for (int j = 0; j < 4; j++)
                    mma_f16(acc[i][j], af[i], bf[j]);
        }
        if (c + 1 < nchunks) store_chunk(b ^ 1);
        __syncthreads();
    }

#pragma unroll
    for (int i = 0; i < MT; i++) {
        int row0 = m0 + wm * WM + i * 16 + gr;
#pragma unroll
        for (int j = 0; j < 4; j++) {
            int col = n0 + wn * 32 + j * 8 + tc * 2;
            float b0 = 0.f, b1 = 0.f;
            if (ADD_BIAS) { b0 = bias[col]; b1 = bias[col + 1]; }
            if (OUT_HALF) {
                __half2 v0 = __floats2half2_rn(acc[i][j][0] + b0, acc[i][j][1] + b1);
                __half2 v1 = __floats2half2_rn(acc[i][j][2] + b0, acc[i][j][3] + b1);
                if (row0 < M) *(uint32_t*)(Ch + (size_t)row0 * Nc + col) = *(uint32_t*)&v0;
                if (row0 + 8 < M) *(uint32_t*)(Ch + (size_t)(row0 + 8) * Nc + col) = *(uint32_t*)&v1;
            } else {
                if (row0 < M)
                    *(float2*)(Cf + (size_t)row0 * Nc + col) =
                        make_float2(acc[i][j][0] + b0, acc[i][j][1] + b1);
                if (row0 + 8 < M)
                    *(float2*)(Cf + (size_t)(row0 + 8) * Nc + col) =
                        make_float2(acc[i][j][2] + b0, acc[i][j][3] + b1);
            }
        }
    }

    if (SCORES) {
#pragma unroll
        for (int i = 0; i < MT; i++) {
            float p1a = 0.f, p1b = 0.f, p2a = 0.f, p2b = 0.f;
#pragma unroll
            for (int j = 0; j < 4; j++) {
                int col = wn * 32 + j * 8 + tc * 2;
                float a0 = sa[col], a1 = sa[col + 1];
                float d0 = sd[col], d1 = sd[col + 1];
                p1a += acc[i][j][0] * a0 + acc[i][j][1] * a1;
                p2a += acc[i][j][0] * d0 + acc[i][j][1] * d1;
                p1b += acc[i][j][2] * a0 + acc[i][j][3] * a1;
                p2b += acc[i][j][2] * d0 + acc[i][j][3] * d1;
            }
#pragma unroll
            for (int o = 1; o <= 2; o <<= 1) {
                p1a += __shfl_xor_sync(0xffffffffu, p1a, o);
                p1b += __shfl_xor_sync(0xffffffffu, p1b, o);
                p2a += __shfl_xor_sync(0xffffffffu, p2a, o);
                p2b += __shfl_xor_sync(0xffffffffu, p2b, o);
            }
            if (tc == 0) {
                int rl = wm * WM + i * 16 + gr;
                sSp[wn][rl] = p1a; sSp[wn][rl + 8] = p1b;
                sDp[wn][rl] = p2a; sDp[wn][rl + 8] = p2b;
            }
        }
        __syncthreads();
        if (tid < 128) {
            int row = m0 + tid;
            if (row < M) {
                float s1 = sSp[0][tid] + sSp[1][tid] + sSp[2][tid] + sSp[3][tid];
                float s2 = sDp[0][tid] + sDp[1][tid] + sDp[2][tid] + sDp[3][tid];
                g_ssrc[row * HH + head] = s1;
                g_sdst[row * HH + head] = s2;
            }
        }
    }
}

// ---------------- aggregation via tensor cores ----------------
// Block = 16 dst nodes. Per 16-edge chunk: stage H[16][1024] fp16 + P[head][16][16]
// fp16 (block-diagonal softmax weights), then warp w computes C_w[16,128] += P_w @ H_w
// via mma.m16n8k16 with ldmatrix.x2.trans B-frags (flash-attn P@V pattern).
__global__ void __launch_bounds__(256) k_agg_mma(const __half* __restrict__ h16,
                                                 const float* __restrict__ bias,
                                                 __half* __restrict__ out16) {
    __shared__ __half sH[CHUNK * HSTR];      // 33024 B
    __shared__ __half sP[2 * PBUF];          // 12288 B (double buffered)
    __shared__ float s_z[GROUP][HH];         // 512 B

    const int tid = threadIdx.x;
    const int w = tid >> 5, lane = tid & 31;
    const int gr = lane >> 2, tc = lane & 3;
    const int nb = blockIdx.x * GROUP;
    const int kb = g_row[nb], ke = g_row[nb + GROUP];

    // prologue: zero both P buffers + z
    for (int i = tid; i < 2 * PBUF / 8; i += 256) ((uint4*)sP)[i] = make_uint4(0, 0, 0, 0);
    if (tid < GROUP * HH) ((float*)s_z)[tid] = 0.f;

    float acc[16][4];
#pragma unroll
    for (int j = 0; j < 16; j++) { acc[j][0] = acc[j][1] = acc[j][2] = acc[j][3] = 0.f; }

    const int hr = tid >> 4, hq = tid & 15;   // H staging: 16 threads/row, 8 uint4 each
    const int pe = tid >> 3, ph = tid & 7;    // P fill: (edge, head), tid < 128
    __syncthreads();

    int b = 0;
    for (int e0 = kb; e0 < ke; e0 += CHUNK) {
        int m = ke - e0; if (m > CHUNK) m = CHUNK;
        // ---- phase A: stage H + fill P[b] (pre-zeroed) ----
        {
            uint4 vals[8];
            if (hr < m) {
                const uint4* hrow = (const uint4*)(h16 + (size_t)g_esrc[e0 + hr] * DD);
#pragma unroll
                for (int i = 0; i < 8; i++) vals[i] = hrow[hq + i * 16];
            } else {
#pragma unroll
                for (int i = 0; i < 8; i++) vals[i] = make_uint4(0, 0, 0, 0);
            }
            uint4* drow = (uint4*)(sH + hr * HSTR);
#pragma unroll
            for (int i = 0; i < 8; i++) drow[hq + i * 16] = vals[i];
        }
        if (tid < 128 && pe < m) {
            int pos = e0 + pe;
            int i = g_edst[pos] - nb;
            int s = g_esrc[pos];
            float v = g_ssrc[s * HH + ph] + g_sdst[(nb + i) * HH + ph];
            v = (v > 0.f) ? v : 0.2f * v;
            float p = __expf(v);
            sP[b * PBUF + (ph * GROUP + i) * PSTR + pe] = __float2half_rn(p);
            atomicAdd(&s_z[i][ph], p);
        }
        __syncthreads();

        // ---- phase B: MMA + zero other P buffer ----
        {
            const __half* Pw = sP + b * PBUF + (w * GROUP) * PSTR;
            uint32_t af[4];
            af[0] = *(const uint32_t*)&Pw[gr * PSTR + tc * 2];
            af[1] = *(const uint32_t*)&Pw[(gr + 8) * PSTR + tc * 2];
            af[2] = *(const uint32_t*)&Pw[gr * PSTR + tc * 2 + 8];
            af[3] = *(const uint32_t*)&Pw[(gr + 8) * PSTR + tc * 2 + 8];
            uint32_t baddr = (uint32_t)__cvta_generic_to_shared(
                sH + (lane & 15) * HSTR + w * 128);
#pragma unroll
            for (int j = 0; j < 16; j++) {
                uint32_t b0, b1;
                ldmatrix_x2_trans(b0, b1, baddr + j * 16);   // +8 halves per tile
                uint32_t bf[2] = { b0, b1 };
                mma_f16(acc[j], af, bf);
            }
        }
        {
            uint4* other = (uint4*)(sP + (b ^ 1) * PBUF);
            for (int i = tid; i < PBUF / 8; i += 256) other[i] = make_uint4(0, 0, 0, 0);
        }
        b ^= 1;
        __syncthreads();
    }

    // ---- epilogue ----
    float rz0 = 1.0f / s_z[gr][w];
    float rz1 = 1.0f / s_z[gr + 8][w];
#pragma unroll
    for (int j = 0; j < 16; j++) {
        int col = w * 128 + j * 8 + tc * 2;
        float2 bb = *(const float2*)(bias + col);
        __half2 v0 = __floats2half2_rn(acc[j][0] * rz0 + bb.x, acc[j][1] * rz0 + bb.y);
        __half2 v1 = __floats2half2_rn(acc[j][2] * rz1 + bb.x, acc[j][3] * rz1 + bb.y);
        *(uint32_t*)(out16 + (size_t)(nb + gr) * DD + col) = *(uint32_t*)&v0;
        *(uint32_t*)(out16 + (size_t)(nb + gr + 8) * DD + col) = *(uint32_t*)&v1;
    }
}

// ---------------- host orchestration ----------------
#define SMEM_BM128 ((2 * 128 * 40 + 2 * 128 * 40) * 2)   // 40960 B
#define SMEM_BM32  ((2 * 32 * 40 + 2 * 128 * 40) * 2)    // 25600 B

static void launch_small_h(const __half* A16, int widx, const float* bias, __half* Ch,
                           __half* wt) {
    dim3 grid(1, (NN + 31) / 32);
    k_gemm<32, true, true, true, false><<<grid, 256, SMEM_BM32>>>(
        A16, wt + widx * WSZ, bias, nullptr, nullptr, nullptr, Ch, NN, DD, CC);
}
static void launch_small_f(const __half* A16, int widx, const float* bias, float* Cf,
                           __half* wt) {
    dim3 grid(1, (NN + 31) / 32);
    k_gemm<32, true, true, false, false><<<grid, 256, SMEM_BM32>>>(
        A16, wt + widx * WSZ, bias, nullptr, nullptr, Cf, nullptr, NN, DD, CC);
}
static void launch_big(const __half* A16, int widx, __half* Ch,
                       const float* asrc, const float* adst, __half* wt) {
    dim3 grid(DD / 128, (NN + 127) / 128);
    k_gemm<128, false, false, true, true><<<grid, 256, SMEM_BM128>>>(
        A16, wt + widx * WSZ, nullptr, asrc, adst, nullptr, Ch, NN, CC, DD);
}

extern "C" void kernel_launch(void* const* d_in, const int* in_sizes, int n_in,
                              void* d_out, int out_size) {
    const float* x   = (const float*)d_in[0];
    const int*   ei  = (const int*)d_in[1];
    const float* w1  = (const float*)d_in[2];
    const float* as1 = (const float*)d_in[3];
    const float* ad1 = (const float*)d_in[4];
    const float* b1  = (const float*)d_in[5];
    const float* w2  = (const float*)d_in[6];
    const float* as2 = (const float*)d_in[7];
    const float* ad2 = (const float*)d_in[8];
    const float* b2  = (const float*)d_in[9];
    const float* w3  = (const float*)d_in[10];
    const float* as3 = (const float*)d_in[11];
    const float* ad3 = (const float*)d_in[12];
    const float* b3  = (const float*)d_in[13];
    const float* rw1 = (const float*)d_in[14];
    const float* rb1 = (const float*)d_in[15];
    const float* rw2 = (const float*)d_in[16];
    const float* rb2 = (const float*)d_in[17];
    const float* lw  = (const float*)d_in[18];
    const float* lb  = (const float*)d_in[19];
    float* out = (float*)d_out;

    __half *h16, *agg16, *feat16, *wt;
    cudaGetSymbolAddress((void**)&h16, g_h16);
    cudaGetSymbolAddress((void**)&agg16, g_agg16);
    cudaGetSymbolAddress((void**)&feat16, g_feat16);
    cudaGetSymbolAddress((void**)&wt, g_wt);

    cudaFuncSetAttribute((const void*)k_gemm<32, true, true, true, false>,
                         cudaFuncAttributeMaxDynamicSharedMemorySize, SMEM_BM32);
    cudaFuncSetAttribute((const void*)k_gemm<32, true, true, false, false>,
                         cudaFuncAttributeMaxDynamicSharedMemorySize, SMEM_BM32);
    cudaFuncSetAttribute((const void*)k_gemm<128, false, false, true, true>,
                         cudaFuncAttributeMaxDynamicSharedMemorySize, SMEM_BM128);

    // upfront: weights + CSR count (fused), scan, then fill + layer-1 (fused)
    k_cvt_count<<<(5 * WSZ + 255) / 256, 256>>>(rw1, w2, rw2, w3, lw, ei);
    k_scan<<<1, 1024>>>();
    k_fill_l1<<<665 + NN, 256>>>(ei, x, w1, as1, ad1, h16);

    // layer 1 aggregate
    k_agg_mma<<<NN / GROUP, 256>>>(h16, b1, agg16);

    // layer 2
    launch_small_h(agg16, 0, rb1, feat16, wt);
    launch_big(feat16, 1, h16, as2, ad2, wt);
    k_agg_mma<<<NN / GROUP, 256>>>(h16, b2, agg16);

    // layer 3
    launch_small_h(agg16, 2, rb2, feat16, wt);
    launch_big(feat16, 3, h16, as3, ad3, wt);
    k_agg_mma<<<NN / GROUP, 256>>>(h16, b3, agg16);

    // final projection
    launch_small_f(agg16, 4, lb, out, wt);
}

// round 14
// speedup vs baseline: 1.5390x; 1.5390x over previous
#include <cuda_runtime.h>
#include <cuda_fp16.h>
#include <math.h>
#include <stdint.h>

#define NN 10000
#define EE 160000
#define ETOT 170000   // EE + NN self loops
#define HH 8
#define CC 128
#define DD 1024
#define WSZ (DD * CC) // 131072 elements per weight matrix

// ---------------- scratch (static device memory; no allocations) ----------------
__device__ float  g_h32[NN * DD];     // fp32 per-layer h (gather source)
__device__ __half g_agg16[NN * DD];   // fp16 aggregate output (feeds small GEMM)
__device__ __half g_feat16[NN * CC];  // fp16 feat (small GEMM out, big GEMM in)
__device__ float g_ssrc[NN * HH];
__device__ float g_sdst[NN * HH];
__device__ int   g_cnt[NN];           // BSS-zeroed; re-zeroed by k_scan each call
__device__ int   g_row[NN + 1];
__device__ int   g_cur[NN];
__device__ int   g_esrc[ETOT];        // src node per CSR position
__device__ __half g_wt[5 * WSZ];      // transposed fp16 weights [Nc,K]

__device__ __forceinline__ float gelu_exact(float x) {
    return x * normcdff(x);   // jax.nn.gelu(approximate=False)
}
__device__ __forceinline__ int edge_src(const int* ei, int e) {
    return (e < EE) ? ei[e] : (e - EE);
}
__device__ __forceinline__ int edge_dst(const int* ei, int e) {
    return (e < EE) ? ei[EE + e] : (e - EE);
}

// ---------------- fused: weight convert+transpose AND edge counting ----------------
__global__ void k_cvt_count(const float* __restrict__ w0, const float* __restrict__ w1_,
                            const float* __restrict__ w2_, const float* __restrict__ w3_,
                            const float* __restrict__ w4_, const int* __restrict__ ei) {
    int idx = blockIdx.x * 256 + threadIdx.x;
    if (idx < 5 * WSZ) {
        int which = idx / WSZ, r = idx - which * WSZ;
        const float* W;
        int K, Nc;
        switch (which) {
            case 0: W = w0;  K = 1024; Nc = 128;  break;
            case 1: W = w1_; K = 128;  Nc = 1024; break;
            case 2: W = w2_; K = 1024; Nc = 128;  break;
            case 3: W = w3_; K = 128;  Nc = 1024; break;
            default: W = w4_; K = 1024; Nc = 128; break;
        }
        int k = r / Nc, n = r - k * Nc;
        g_wt[which * WSZ + n * K + k] = __float2half_rn(W[r]);
    }
    if (idx < ETOT) atomicAdd(&g_cnt[edge_dst(ei, idx)], 1);
}

__global__ void k_scan() {
    __shared__ int sh[1024];
    int t = threadIdx.x;
    int base = t * 10;
    int cnt[10];
    int s = 0;
#pragma unroll
    for (int i = 0; i < 10; i++) {
        int j = base + i;
        cnt[i] = (j < NN) ? g_cnt[j] : 0;
        s += cnt[i];
        if (j < NN) g_cnt[j] = 0;
    }
    sh[t] = s;
    __syncthreads();
    for (int off = 1; off < 1024; off <<= 1) {
        int v = (t >= off) ? sh[t - off] : 0;
        __syncthreads();
        sh[t] += v;
        __syncthreads();
    }
    int run = sh[t] - s;
    for (int i = 0; i < 10; i++) {
        int j = base + i;
        if (j < NN) { g_row[j] = run; g_cur[j] = run; run += cnt[i]; }
    }
    if (t == 1023) g_row[NN] = sh[1023];
}

// ---------------- fused: CSR fill (blocks 0..664) + layer-1 h/scores (blocks 665..) ----------------
__global__ void __launch_bounds__(256) k_fill_l1(const int* __restrict__ ei,
                                                 const float* __restrict__ x,
                                                 const float* __restrict__ w1,
                                                 const float* __restrict__ asrc,
                                                 const float* __restrict__ adst,
                                                 float* __restrict__ h32) {
    if (blockIdx.x < 665) {
        int e = blockIdx.x * 256 + threadIdx.x;
        if (e < ETOT) {
            int pos = atomicAdd(&g_cur[edge_dst(ei, e)], 1);
            g_esrc[pos] = edge_src(ei, e);
        }
        return;
    }
    int n = blockIdx.x - 665;
    int w = threadIdx.x >> 5, lane = threadIdx.x & 31;
    float4 xv = *(const float4*)(x + n * 4);
    int db = w * CC + lane * 4;
    float4 c0 = *(const float4*)(w1 + 0 * DD + db);
    float4 c1 = *(const float4*)(w1 + 1 * DD + db);
    float4 c2 = *(const float4*)(w1 + 2 * DD + db);
    float4 c3 = *(const float4*)(w1 + 3 * DD + db);
    float h0 = xv.x * c0.x + xv.y * c1.x + xv.z * c2.x + xv.w * c3.x;
    float h1 = xv.x * c0.y + xv.y * c1.y + xv.z * c2.y + xv.w * c3.y;
    float h2 = xv.x * c0.z + xv.y * c1.z + xv.z * c2.z + xv.w * c3.z;
    float h3 = xv.x * c0.w + xv.y * c1.w + xv.z * c2.w + xv.w * c3.w;
    *(float4*)(h32 + (size_t)n * DD + db) = make_float4(h0, h1, h2, h3);

    float4 a = *(const float4*)(asrc + db);
    float4 d = *(const float4*)(adst + db);
    float s1 = h0 * a.x + h1 * a.y + h2 * a.z + h3 * a.w;
    float s2 = h0 * d.x + h1 * d.y + h2 * d.z + h3 * d.w;
#pragma unroll
    for (int o = 16; o > 0; o >>= 1) {
        s1 += __shfl_xor_sync(0xffffffffu, s1, o);
        s2 += __shfl_xor_sync(0xffffffffu, s2, o);
    }
    if (lane == 0) {
        g_ssrc[n * HH + w] = s1;
        g_sdst[n * HH + w] = s2;
    }
}

// ---------------- fp16 GEMM, double-buffered smem ----------------
__device__ __forceinline__ void mma_f16(float* c, const uint32_t* a, const uint32_t* b) {
    asm volatile(
        "mma.sync.aligned.m16n8k16.row.col.f32.f16.f16.f32 "
        "{%0,%1,%2,%3}, {%4,%5,%6,%7}, {%8,%9}, {%0,%1,%2,%3};"
        : "+f"(c[0]), "+f"(c[1]), "+f"(c[2]), "+f"(c[3])
        : "r"(a[0]), "r"(a[1]), "r"(a[2]), "r"(a[3]), "r"(b[0]), "r"(b[1]));
}

template <int BM, bool GELU_A, bool ADD_BIAS, bool OUT_HALF, bool SCORES>
__global__ void __launch_bounds__(256) k_gemm(
    const __half* __restrict__ Ahg, const __half* __restrict__ Bg,
    const float* __restrict__ bias,
    const float* __restrict__ asrc, const float* __restrict__ adst,
    float* __restrict__ Cf, __half* __restrict__ Ch, int M, int K, int Nc) {
    constexpr int STR = 40;
    constexpr int WM = BM / 2;
    constexpr int MT = WM / 16;

    extern __shared__ __half dsm[];
    __half* AsB = dsm;
    __half* BsB = dsm + 2 * BM * STR;
    __shared__ float sa[128], sd[128];
    __shared__ float sSp[4][128], sDp[4][128];

    const int tid = threadIdx.x;
    const int wid = tid >> 5, lane = tid & 31;
    const int wm = wid & 1, wn = wid >> 1;
    const int gr = lane >> 2, tc = lane & 3;
    const int m0 = blockIdx.y * BM, n0 = blockIdx.x * 128;
    const int head = blockIdx.x;

    if (SCORES && tid < 128) {
        sa[tid] = asrc[head * 128 + tid];
        sd[tid] = adst[head * 128 + tid];
    }

    float acc[MT][4][4];
#pragma unroll
    for (int i = 0; i < MT; i++)
#pragma unroll
        for (int j = 0; j < 4; j++)
#pragma unroll
            for (int q = 0; q < 4; q++) acc[i][j][q] = 0.f;

    uint4 rAh128[2];
    uint2 rAh32;
    uint4 rB[2];
    const int ar128 = tid >> 1, aq128 = (tid & 1) * 2;
    const int ar32 = tid >> 3, aq32 = tid & 7;
    const int br_ = tid >> 1, bq_ = tid & 1;

    auto load_chunk = [&](int k0) {
        if (BM == 128) {
#pragma unroll
            for (int it = 0; it < 2; it++) {
                int q = aq128 + it;
                rAh128[it] = (m0 + ar128 < M)
                    ? *(const uint4*)(Ahg + (size_t)(m0 + ar128) * K + k0 + q * 8)
                    : make_uint4(0, 0, 0, 0);
            }
        } else {
            rAh32 = (m0 + ar32 < M)
                ? *(const uint2*)(Ahg + (size_t)(m0 + ar32) * K + k0 + aq32 * 4)
                : make_uint2(0, 0);
        }
#pragma unroll
        for (int it = 0; it < 2; it++) {
            int q = bq_ + it * 2;
            rB[it] = *(const uint4*)(Bg + (size_t)(n0 + br_) * K + k0 + q * 8);
        }
    };
    auto store_chunk = [&](int stage) {
        __half* As = AsB + stage * BM * STR;
        __half* Bs = BsB + stage * 128 * STR;
        if (BM == 128) {
#pragma unroll
            for (int it = 0; it < 2; it++) {
                int q = aq128 + it;
                *(uint4*)&As[ar128 * STR + q * 8] = rAh128[it];
            }
        } else {
            uint2 v = rAh32;
            if (GELU_A) {
                __half2 x01 = *(__half2*)&v.x;
                __half2 x23 = *(__half2*)&v.y;
                float2 f01 = __half22float2(x01);
                float2 f23 = __half22float2(x23);
                __half2 g01 = __floats2half2_rn(gelu_exact(f01.x), gelu_exact(f01.y));
                __half2 g23 = __floats2half2_rn(gelu_exact(f23.x), gelu_exact(f23.y));
                v = make_uint2(*(uint32_t*)&g01, *(uint32_t*)&g23);
            }
            *(uint2*)&As[ar32 * STR + aq32 * 4] = v;
        }
#pragma unroll
        for (int it = 0; it < 2; it++) {
            int q = bq_ + it * 2;
            *(uint4*)&Bs[br_ * STR + q * 8] = rB[it];
        }
    };

    const int nchunks = K >> 5;
    load_chunk(0);
    store_chunk(0);
    __syncthreads();

    for (int c = 0; c < nchunks; c++) {
        int b = c & 1;
        if (c + 1 < nchunks) load_chunk((c + 1) << 5);

        const __half* As = AsB + b * BM * STR;
        const __half* Bs = BsB + b * 128 * STR;
#pragma unroll
        for (int ks = 0; ks < 32; ks += 16) {
            uint32_t af[MT][4], bf[4][2];
#pragma unroll
            for (int i = 0; i < MT; i++) {
                int row = wm * WM + i * 16 + gr;
                int o = row * STR + ks + tc * 2;
                af[i][0] = *(const uint32_t*)&As[o];
                af[i][1] = *(const uint32_t*)&As[o + 8 * STR];
                af[i][2] = *(const uint32_t*)&As[o + 8];
                af[i][3] = *(const uint32_t*)&As[o + 8 * STR + 8];
            }
#pragma unroll
            for (int j = 0; j < 4; j++) {
                int nrow = wn * 32 + j * 8 + gr;
                int o = nrow * STR + ks + tc * 2;
                bf[j][0] = *(const uint32_t*)&Bs[o];
                bf[j][1] = *(const uint32_t*)&Bs[o + 8];
            }
#pragma unroll
            for (int i = 0; i < MT; i++)
#pragma unroll
                for (int j = 0; j < 4; j++)
                    mma_f16(acc[i][j], af[i], bf[j]);
        }
        if (c + 1 < nchunks) store_chunk(b ^ 1);
        __syncthreads();
    }

#pragma unroll
    for (int i = 0; i < MT; i++) {
        int row0 = m0 + wm * WM + i * 16 + gr;
#pragma unroll
        for (int j = 0; j < 4; j++) {
            int col = n0 + wn * 32 + j * 8 + tc * 2;
            float b0 = 0.f, b1 = 0.f;
            if (ADD_BIAS) { b0 = bias[col]; b1 = bias[col + 1]; }
            if (OUT_HALF) {
                __half2 v0 = __floats2half2_rn(acc[i][j][0] + b0, acc[i][j][1] + b1);
                __half2 v1 = __floats2half2_rn(acc[i][j][2] + b0, acc[i][j][3] + b1);
                if (row0 < M) *(uint32_t*)(Ch + (size_t)row0 * Nc + col) = *(uint32_t*)&v0;
                if (row0 + 8 < M) *(uint32_t*)(Ch + (size_t)(row0 + 8) * Nc + col) = *(uint32_t*)&v1;
            } else {
                if (row0 < M)
                    *(float2*)(Cf + (size_t)row0 * Nc + col) =
                        make_float2(acc[i][j][0] + b0, acc[i][j][1] + b1);
                if (row0 + 8 < M)
                    *(float2*)(Cf + (size_t)(row0 + 8) * Nc + col) =
                        make_float2(acc[i][j][2] + b0, acc[i][j][3] + b1);
            }
        }
    }

    if (SCORES) {
#pragma unroll
        for (int i = 0; i < MT; i++) {
            float p1a = 0.f, p1b = 0.f, p2a = 0.f, p2b = 0.f;
#pragma unroll
            for (int j = 0; j < 4; j++) {
                int col = wn * 32 + j * 8 + tc * 2;
                float a0 = sa[col], a1 = sa[col + 1];
                float d0 = sd[col], d1 = sd[col + 1];
                p1a += acc[i][j][0] * a0 + acc[i][j][1] * a1;
                p2a += acc[i][j][0] * d0 + acc[i][j][1] * d1;
                p1b += acc[i][j][2] * a0 + acc[i][j][3] * a1;
                p2b += acc[i][j][2] * d0 + acc[i][j][3] * d1;
            }
#pragma unroll
            for (int o = 1; o <= 2; o <<= 1) {
                p1a += __shfl_xor_sync(0xffffffffu, p1a, o);
                p1b += __shfl_xor_sync(0xffffffffu, p1b, o);
                p2a += __shfl_xor_sync(0xffffffffu, p2a, o);
                p2b += __shfl_xor_sync(0xffffffffu, p2b, o);
            }
            if (tc == 0) {
                int rl = wm * WM + i * 16 + gr;
                sSp[wn][rl] = p1a; sSp[wn][rl + 8] = p1b;
                sDp[wn][rl] = p2a; sDp[wn][rl + 8] = p2b;
            }
        }
        __syncthreads();
        if (tid < 128) {
            int row = m0 + tid;
            if (row < M) {
                float s1 = sSp[0][tid] + sSp[1][tid] + sSp[2][tid] + sSp[3][tid];
                float s2 = sDp[0][tid] + sDp[1][tid] + sDp[2][tid] + sDp[3][tid];
                g_ssrc[row * HH + head] = s1;
                g_sdst[row * HH + head] = s2;
            }
        }
    }
}

// ---------------- fused softmax + aggregation v3 ----------------
// 128 threads / node. Warp w covers heads 2w,2w+1 (8 fp32 dims per lane).
// Per 16-edge batch: lanes 0-15 compute p for head 2w, lanes 16-31 for head 2w+1
// (exactly one exp per (edge,head)); consumed via shfl. No smem, no block barriers.
__global__ void __launch_bounds__(128) k_aggregate(const float* __restrict__ h32,
                                                   const float* __restrict__ bias,
                                                   __half* __restrict__ out16) {
    int n = blockIdx.x;
    int w = threadIdx.x >> 5, lane = threadIdx.x & 31;
    int kb = g_row[n], ke = g_row[n + 1];
    int head = 2 * w + (lane >> 4);
    float sdst_h = g_sdst[n * HH + head];

    const float* hb0 = h32 + 256 * w + lane * 4;        // head 2w slice
    const float* hb1 = h32 + 256 * w + 128 + lane * 4;  // head 2w+1 slice

    float z0 = 0.f, z1 = 0.f;
    float4 a0 = make_float4(0.f, 0.f, 0.f, 0.f);
    float4 a1 = make_float4(0.f, 0.f, 0.f, 0.f);

    for (int e0 = kb; e0 < ke; e0 += 16) {
        int m = min(16, ke - e0);
        int ee = e0 + (lane & 15);
        int s_l = (ee < ke) ? g_esrc[ee] : 0;
        float v = g_ssrc[s_l * HH + head] + sdst_h;
        v = (v > 0.f) ? v : 0.2f * v;
        float p_l = __expf(v);
        for (int e = 0; e < m; e++) {
            int s = __shfl_sync(0xffffffffu, s_l, e);
            float p0 = __shfl_sync(0xffffffffu, p_l, e);
            float p1 = __shfl_sync(0xffffffffu, p_l, 16 + e);
            z0 += p0; z1 += p1;
            float4 h0 = *(const float4*)(hb0 + (size_t)s * DD);
            float4 h1 = *(const float4*)(hb1 + (size_t)s * DD);
            a0.x += p0 * h0.x; a0.y += p0 * h0.y; a0.z += p0 * h0.z; a0.w += p0 * h0.w;
            a1.x += p1 * h1.x; a1.y += p1 * h1.y; a1.z += p1 * h1.z; a1.w += p1 * h1.w;
        }
    }

    float rz0 = 1.0f / z0, rz1 = 1.0f / z1;
    int col0 = 256 * w + lane * 4;
    float4 b0 = *(const float4*)(bias + col0);
    float4 b1 = *(const float4*)(bias + col0 + 128);
    __half2 o00 = __floats2half2_rn(a0.x * rz0 + b0.x, a0.y * rz0 + b0.y);
    __half2 o01 = __floats2half2_rn(a0.z * rz0 + b0.z, a0.w * rz0 + b0.w);
    __half2 o10 = __floats2half2_rn(a1.x * rz1 + b1.x, a1.y * rz1 + b1.y);
    __half2 o11 = __floats2half2_rn(a1.z * rz1 + b1.z, a1.w * rz1 + b1.w);
    *(uint2*)(out16 + (size_t)n * DD + col0) = make_uint2(*(uint32_t*)&o00, *(uint32_t*)&o01);
    *(uint2*)(out16 + (size_t)n * DD + col0 + 128) = make_uint2(*(uint32_t*)&o10, *(uint32_t*)&o11);
}

// ---------------- host orchestration ----------------
#define SMEM_BM128 ((2 * 128 * 40 + 2 * 128 * 40) * 2)   // 40960 B
#define SMEM_BM32  ((2 * 32 * 40 + 2 * 128 * 40) * 2)    // 25600 B

static void launch_small_h(const __half* A16, int widx, const float* bias, __half* Ch,
                           __half* wt) {
    dim3 grid(1, (NN + 31) / 32);
    k_gemm<32, true, true, true, false><<<grid, 256, SMEM_BM32>>>(
        A16, wt + widx * WSZ, bias, nullptr, nullptr, nullptr, Ch, NN, DD, CC);
}
static void launch_small_f(const __half* A16, int widx, const float* bias, float* Cf,
                           __half* wt) {
    dim3 grid(1, (NN + 31) / 32);
    k_gemm<32, true, true, false, false><<<grid, 256, SMEM_BM32>>>(
        A16, wt + widx * WSZ, bias, nullptr, nullptr, Cf, nullptr, NN, DD, CC);
}
static void launch_big(const __half* A16, int widx, float* Cf,
                       const float* asrc, const float* adst, __half* wt) {
    dim3 grid(DD / 128, (NN + 127) / 128);
    k_gemm<128, false, false, false, true><<<grid, 256, SMEM_BM128>>>(
        A16, wt + widx * WSZ, nullptr, asrc, adst, Cf, nullptr, NN, CC, DD);
}

extern "C" void kernel_launch(void* const* d_in, const int* in_sizes, int n_in,
                              void* d_out, int out_size) {
    const float* x   = (const float*)d_in[0];
    const int*   ei  = (const int*)d_in[1];
    const float* w1  = (const float*)d_in[2];
    const float* as1 = (const float*)d_in[3];
    const float* ad1 = (const float*)d_in[4];
    const float* b1  = (const float*)d_in[5];
    const float* w2  = (const float*)d_in[6];
    const float* as2 = (const float*)d_in[7];
    const float* ad2 = (const float*)d_in[8];
    const float* b2  = (const float*)d_in[9];
    const float* w3  = (const float*)d_in[10];
    const float* as3 = (const float*)d_in[11];
    const float* ad3 = (const float*)d_in[12];
    const float* b3  = (const float*)d_in[13];
    const float* rw1 = (const float*)d_in[14];
    const float* rb1 = (const float*)d_in[15];
    const float* rw2 = (const float*)d_in[16];
    const float* rb2 = (const float*)d_in[17];
    const float* lw  = (const float*)d_in[18];
    const float* lb  = (const float*)d_in[19];
    float* out = (float*)d_out;

    float* h32;
    __half *agg16, *feat16, *wt;
    cudaGetSymbolAddress((void**)&h32, g_h32);
    cudaGetSymbolAddress((void**)&agg16, g_agg16);
    cudaGetSymbolAddress((void**)&feat16, g_feat16);
    cudaGetSymbolAddress((void**)&wt, g_wt);

    cudaFuncSetAttribute((const void*)k_gemm<32, true, true, true, false>,
                         cudaFuncAttributeMaxDynamicSharedMemorySize, SMEM_BM32);
    cudaFuncSetAttribute((const void*)k_gemm<32, true, true, false, false>,
                         cudaFuncAttributeMaxDynamicSharedMemorySize, SMEM_BM32);
    cudaFuncSetAttribute((const void*)k_gemm<128, false, false, false, true>,
                         cudaFuncAttributeMaxDynamicSharedMemorySize, SMEM_BM128);

    // upfront: weights + CSR count (fused), scan, then fill + layer-1 (fused)
    k_cvt_count<<<(5 * WSZ + 255) / 256, 256>>>(rw1, w2, rw2, w3, lw, ei);
    k_scan<<<1, 1024>>>();
    k_fill_l1<<<665 + NN, 256>>>(ei, x, w1, as1, ad1, h32);

    // layer 1 aggregate
    k_aggregate<<<NN, 128>>>(h32, b1, agg16);

    // layer 2
    launch_small_h(agg16, 0, rb1, feat16, wt);
    launch_big(feat16, 1, h32, as2, ad2, wt);
    k_aggregate<<<NN, 128>>>(h32, b2, agg16);

    // layer 3
    launch_small_h(agg16, 2, rb2, feat16, wt);
    launch_big(feat16, 3, h32, as3, ad3, wt);
    k_aggregate<<<NN, 128>>>(h32, b3, agg16);

    // final projection
    launch_small_f(agg16, 4, lb, out, wt);
}

// round 15
// speedup vs baseline: 1.6392x; 1.0651x over previous
#include <cuda_runtime.h>
#include <cuda_fp16.h>
#include <math.h>
#include <stdint.h>

#define NN 10000
#define EE 160000
#define ETOT 170000   // EE + NN self loops
#define HH 8
#define CC 128
#define DD 1024
#define WSZ (DD * CC) // 131072 elements per weight matrix

// ---------------- scratch (static device memory; no allocations) ----------------
__device__ __half g_h16[NN * DD];     // fp16 per-layer h (gather + scores source)
__device__ __half g_agg16[NN * DD];   // fp16 aggregate output (feeds small GEMM)
__device__ __half g_feat16[NN * CC];  // fp16 feat (small GEMM out, big GEMM in)
__device__ float g_ssrc[NN * HH];
__device__ float g_sdst[NN * HH];
__device__ int   g_cnt[NN];           // BSS-zeroed; re-zeroed by k_scan each call
__device__ int   g_row[NN + 1];
__device__ int   g_cur[NN];
__device__ int   g_esrc[ETOT];        // src node per CSR position
__device__ __half g_wt[5 * WSZ];      // transposed fp16 weights [Nc,K]

__device__ __forceinline__ float gelu_exact(float x) {
    return x * normcdff(x);   // jax.nn.gelu(approximate=False)
}
__device__ __forceinline__ int edge_src(const int* ei, int e) {
    return (e < EE) ? ei[e] : (e - EE);
}
__device__ __forceinline__ int edge_dst(const int* ei, int e) {
    return (e < EE) ? ei[EE + e] : (e - EE);
}

// ---------------- fused: weight convert+transpose AND edge counting ----------------
__global__ void k_cvt_count(const float* __restrict__ w0, const float* __restrict__ w1_,
                            const float* __restrict__ w2_, const float* __restrict__ w3_,
                            const float* __restrict__ w4_, const int* __restrict__ ei) {
    int idx = blockIdx.x * 256 + threadIdx.x;
    if (idx < 5 * WSZ) {
        int which = idx / WSZ, r = idx - which * WSZ;
        const float* W;
        int K, Nc;
        switch (which) {
            case 0: W = w0;  K = 1024; Nc = 128;  break;
            case 1: W = w1_; K = 128;  Nc = 1024; break;
            case 2: W = w2_; K = 1024; Nc = 128;  break;
            case 3: W = w3_; K = 128;  Nc = 1024; break;
            default: W = w4_; K = 1024; Nc = 128; break;
        }
        int k = r / Nc, n = r - k * Nc;
        g_wt[which * WSZ + n * K + k] = __float2half_rn(W[r]);
    }
    if (idx < ETOT) atomicAdd(&g_cnt[edge_dst(ei, idx)], 1);
}

__global__ void k_scan() {
    __shared__ int sh[1024];
    int t = threadIdx.x;
    int base = t * 10;
    int cnt[10];
    int s = 0;
#pragma unroll
    for (int i = 0; i < 10; i++) {
        int j = base + i;
        cnt[i] = (j < NN) ? g_cnt[j] : 0;
        s += cnt[i];
        if (j < NN) g_cnt[j] = 0;
    }
    sh[t] = s;
    __syncthreads();
    for (int off = 1; off < 1024; off <<= 1) {
        int v = (t >= off) ? sh[t - off] : 0;
        __syncthreads();
        sh[t] += v;
        __syncthreads();
    }
    int run = sh[t] - s;
    for (int i = 0; i < 10; i++) {
        int j = base + i;
        if (j < NN) { g_row[j] = run; g_cur[j] = run; run += cnt[i]; }
    }
    if (t == 1023) g_row[NN] = sh[1023];
}

// ---------------- fused: CSR fill (blocks 0..664) + layer-1 h/scores (blocks 665..) ----------------
__global__ void __launch_bounds__(256) k_fill_l1(const int* __restrict__ ei,
                                                 const float* __restrict__ x,
                                                 const float* __restrict__ w1,
                                                 const float* __restrict__ asrc,
                                                 const float* __restrict__ adst,
                                                 __half* __restrict__ h16) {
    if (blockIdx.x < 665) {
        int e = blockIdx.x * 256 + threadIdx.x;
        if (e < ETOT) {
            int pos = atomicAdd(&g_cur[edge_dst(ei, e)], 1);
            g_esrc[pos] = edge_src(ei, e);
        }
        return;
    }
    int n = blockIdx.x - 665;
    int w = threadIdx.x >> 5, lane = threadIdx.x & 31;
    float4 xv = *(const float4*)(x + n * 4);
    int db = w * CC + lane * 4;
    float4 c0 = *(const float4*)(w1 + 0 * DD + db);
    float4 c1 = *(const float4*)(w1 + 1 * DD + db);
    float4 c2 = *(const float4*)(w1 + 2 * DD + db);
    float4 c3 = *(const float4*)(w1 + 3 * DD + db);
    float h0 = xv.x * c0.x + xv.y * c1.x + xv.z * c2.x + xv.w * c3.x;
    float h1 = xv.x * c0.y + xv.y * c1.y + xv.z * c2.y + xv.w * c3.y;
    float h2 = xv.x * c0.z + xv.y * c1.z + xv.z * c2.z + xv.w * c3.z;
    float h3 = xv.x * c0.w + xv.y * c1.w + xv.z * c2.w + xv.w * c3.w;
    __half2 p01 = __floats2half2_rn(h0, h1);
    __half2 p23 = __floats2half2_rn(h2, h3);
    *(uint2*)(h16 + (size_t)n * DD + db) =
        make_uint2(*(uint32_t*)&p01, *(uint32_t*)&p23);

    float4 a = *(const float4*)(asrc + db);
    float4 d = *(const float4*)(adst + db);
    float s1 = h0 * a.x + h1 * a.y + h2 * a.z + h3 * a.w;
    float s2 = h0 * d.x + h1 * d.y + h2 * d.z + h3 * d.w;
#pragma unroll
    for (int o = 16; o > 0; o >>= 1) {
        s1 += __shfl_xor_sync(0xffffffffu, s1, o);
        s2 += __shfl_xor_sync(0xffffffffu, s2, o);
    }
    if (lane == 0) {
        g_ssrc[n * HH + w] = s1;
        g_sdst[n * HH + w] = s2;
    }
}

// ---------------- fp16 GEMM, double-buffered smem ----------------
__device__ __forceinline__ void mma_f16(float* c, const uint32_t* a, const uint32_t* b) {
    asm volatile(
        "mma.sync.aligned.m16n8k16.row.col.f32.f16.f16.f32 "
        "{%0,%1,%2,%3}, {%4,%5,%6,%7}, {%8,%9}, {%0,%1,%2,%3};"
        : "+f"(c[0]), "+f"(c[1]), "+f"(c[2]), "+f"(c[3])
        : "r"(a[0]), "r"(a[1]), "r"(a[2]), "r"(a[3]), "r"(b[0]), "r"(b[1]));
}

template <int BM, bool GELU_A, bool ADD_BIAS, bool OUT_HALF, bool SCORES>
__global__ void __launch_bounds__(256) k_gemm(
    const __half* __restrict__ Ahg, const __half* __restrict__ Bg,
    const float* __restrict__ bias,
    const float* __restrict__ asrc, const float* __restrict__ adst,
    float* __restrict__ Cf, __half* __restrict__ Ch, int M, int K, int Nc) {
    constexpr int STR = 40;
    constexpr int WM = BM / 2;
    constexpr int MT = WM / 16;

    extern __shared__ __half dsm[];
    __half* AsB = dsm;
    __half* BsB = dsm + 2 * BM * STR;
    __shared__ float sa[128], sd[128];
    __shared__ float sSp[4][128], sDp[4][128];

    const int tid = threadIdx.x;
    const int wid = tid >> 5, lane = tid & 31;
    const int wm = wid & 1, wn = wid >> 1;
    const int gr = lane >> 2, tc = lane & 3;
    const int m0 = blockIdx.y * BM, n0 = blockIdx.x * 128;
    const int head = blockIdx.x;

    if (SCORES && tid < 128) {
        sa[tid] = asrc[head * 128 + tid];
        sd[tid] = adst[head * 128 + tid];
    }

    float acc[MT][4][4];
#pragma unroll
    for (int i = 0; i < MT; i++)
#pragma unroll
        for (int j = 0; j < 4; j++)
#pragma unroll
            for (int q = 0; q < 4; q++) acc[i][j][q] = 0.f;

    uint4 rAh128[2];
    uint2 rAh32;
    uint4 rB[2];
    const int ar128 = tid >> 1, aq128 = (tid & 1) * 2;
    const int ar32 = tid >> 3, aq32 = tid & 7;
    const int br_ = tid >> 1, bq_ = tid & 1;

    auto load_chunk = [&](int k0) {
        if (BM == 128) {
#pragma unroll
            for (int it = 0; it < 2; it++) {
                int q = aq128 + it;
                rAh128[it] = (m0 + ar128 < M)
                    ? *(const uint4*)(Ahg + (size_t)(m0 + ar128) * K + k0 + q * 8)
                    : make_uint4(0, 0, 0, 0);
            }
        } else {
            rAh32 = (m0 + ar32 < M)
                ? *(const uint2*)(Ahg + (size_t)(m0 + ar32) * K + k0 + aq32 * 4)
                : make_uint2(0, 0);
        }
#pragma unroll
        for (int it = 0; it < 2; it++) {
            int q = bq_ + it * 2;
            rB[it] = *(const uint4*)(Bg + (size_t)(n0 + br_) * K + k0 + q * 8);
        }
    };
    auto store_chunk = [&](int stage) {
        __half* As = AsB + stage * BM * STR;
        __half* Bs = BsB + stage * 128 * STR;
        if (BM == 128) {
#pragma unroll
            for (int it = 0; it < 2; it++) {
                int q = aq128 + it;
                *(uint4*)&As[ar128 * STR + q * 8] = rAh128[it];
            }
        } else {
            uint2 v = rAh32;
            if (GELU_A) {
                __half2 x01 = *(__half2*)&v.x;
                __half2 x23 = *(__half2*)&v.y;
                float2 f01 = __half22float2(x01);
                float2 f23 = __half22float2(x23);
                __half2 g01 = __floats2half2_rn(gelu_exact(f01.x), gelu_exact(f01.y));
                __half2 g23 = __floats2half2_rn(gelu_exact(f23.x), gelu_exact(f23.y));
                v = make_uint2(*(uint32_t*)&g01, *(uint32_t*)&g23);
            }
            *(uint2*)&As[ar32 * STR + aq32 * 4] = v;
        }
#pragma unroll
        for (int it = 0; it < 2; it++) {
            int q = bq_ + it * 2;
            *(uint4*)&Bs[br_ * STR + q * 8] = rB[it];
        }
    };

    const int nchunks = K >> 5;
    load_chunk(0);
    store_chunk(0);
    __syncthreads();

    for (int c = 0; c < nchunks; c++) {
        int b = c & 1;
        if (c + 1 < nchunks) load_chunk((c + 1) << 5);

        const __half* As = AsB + b * BM * STR;
        const __half* Bs = BsB + b * 128 * STR;
#pragma unroll
        for (int ks = 0; ks < 32; ks += 16) {
            uint32_t af[MT][4], bf[4][2];
#pragma unroll
            for (int i = 0; i < MT; i++) {
                int row = wm * WM + i * 16 + gr;
                int o = row * STR + ks + tc * 2;
                af[i][0] = *(const uint32_t*)&As[o];
                af[i][1] = *(const uint32_t*)&As[o + 8 * STR];
                af[i][2] = *(const uint32_t*)&As[o + 8];
                af[i][3] = *(const uint32_t*)&As[o + 8 * STR + 8];
            }
#pragma unroll
            for (int j = 0; j < 4; j++) {
                int nrow = wn * 32 + j * 8 + gr;
                int o = nrow * STR + ks + tc * 2;
                bf[j][0] = *(const uint32_t*)&Bs[o];
                bf[j][1] = *(const uint32_t*)&Bs[o + 8];
            }
#pragma unroll
            for (int i = 0; i < MT; i++)
#pragma unroll
                for (int j = 0; j < 4; j++)
                    mma_f16(acc[i][j], af[i], bf[j]);
        }
        if (c + 1 < nchunks) store_chunk(b ^ 1);
        __syncthreads();
    }

#pragma unroll
    for (int i = 0; i < MT; i++) {
        int row0 = m0 + wm * WM + i * 16 + gr;
#pragma unroll
        for (int j = 0; j < 4; j++) {
            int col = n0 + wn * 32 + j * 8 + tc * 2;
            float b0 = 0.f, b1 = 0.f;
            if (ADD_BIAS) { b0 = bias[col]; b1 = bias[col + 1]; }
            if (OUT_HALF) {
                __half2 v0 = __floats2half2_rn(acc[i][j][0] + b0, acc[i][j][1] + b1);
                __half2 v1 = __floats2half2_rn(acc[i][j][2] + b0, acc[i][j][3] + b1);
                if (row0 < M) *(uint32_t*)(Ch + (size_t)row0 * Nc + col) = *(uint32_t*)&v0;
                if (row0 + 8 < M) *(uint32_t*)(Ch + (size_t)(row0 + 8) * Nc + col) = *(uint32_t*)&v1;
            } else {
                if (row0 < M)
                    *(float2*)(Cf + (size_t)row0 * Nc + col) =
                        make_float2(acc[i][j][0] + b0, acc[i][j][1] + b1);
                if (row0 + 8 < M)
                    *(float2*)(Cf + (size_t)(row0 + 8) * Nc + col) =
                        make_float2(acc[i][j][2] + b0, acc[i][j][3] + b1);
            }
        }
    }

    if (SCORES) {
#pragma unroll
        for (int i = 0; i < MT; i++) {
            float p1a = 0.f, p1b = 0.f, p2a = 0.f, p2b = 0.f;
#pragma unroll
            for (int j = 0; j < 4; j++) {
                int col = wn * 32 + j * 8 + tc * 2;
                float a0 = sa[col], a1 = sa[col + 1];
                float d0 = sd[col], d1 = sd[col + 1];
                p1a += acc[i][j][0] * a0 + acc[i][j][1] * a1;
                p2a += acc[i][j][0] * d0 + acc[i][j][1] * d1;
                p1b += acc[i][j][2] * a0 + acc[i][j][3] * a1;
                p2b += acc[i][j][2] * d0 + acc[i][j][3] * d1;
            }
#pragma unroll
            for (int o = 1; o <= 2; o <<= 1) {
                p1a += __shfl_xor_sync(0xffffffffu, p1a, o);
                p1b += __shfl_xor_sync(0xffffffffu, p1b, o);
                p2a += __shfl_xor_sync(0xffffffffu, p2a, o);
                p2b += __shfl_xor_sync(0xffffffffu, p2b, o);
            }
            if (tc == 0) {
                int rl = wm * WM + i * 16 + gr;
                sSp[wn][rl] = p1a; sSp[wn][rl + 8] = p1b;
                sDp[wn][rl] = p2a; sDp[wn][rl + 8] = p2b;
            }
        }
        __syncthreads();
        if (tid < 128) {
            int row = m0 + tid;
            if (row < M) {
                float s1 = sSp[0][tid] + sSp[1][tid] + sSp[2][tid] + sSp[3][tid];
                float s2 = sDp[0][tid] + sDp[1][tid] + sDp[2][tid] + sDp[3][tid];
                g_ssrc[row * HH + head] = s1;
                g_sdst[row * HH + head] = s2;
            }
        }
    }
}

// ---------------- fused softmax + aggregation v4: v3 structure + fp16 gather ----------------
// 128 threads / node. Warp w covers heads 2w,2w+1 (8 dims per lane).
// Per 16-edge batch: lanes 0-15 compute p for head 2w, lanes 16-31 for head 2w+1;
// consumed via shfl. No smem, no block barriers. Gather payload fp16 (halved bytes).
__global__ void __launch_bounds__(128) k_aggregate(const __half* __restrict__ h16,
                                                   const float* __restrict__ bias,
                                                   __half* __restrict__ out16) {
    int n = blockIdx.x;
    int w = threadIdx.x >> 5, lane = threadIdx.x & 31;
    int kb = g_row[n], ke = g_row[n + 1];
    int head = 2 * w + (lane >> 4);
    float sdst_h = g_sdst[n * HH + head];

    const __half* hb0 = h16 + 256 * w + lane * 4;        // head 2w slice (4 halves)
    const __half* hb1 = h16 + 256 * w + 128 + lane * 4;  // head 2w+1 slice

    float z0 = 0.f, z1 = 0.f;
    float4 a0 = make_float4(0.f, 0.f, 0.f, 0.f);
    float4 a1 = make_float4(0.f, 0.f, 0.f, 0.f);

    for (int e0 = kb; e0 < ke; e0 += 16) {
        int m = min(16, ke - e0);
        int ee = e0 + (lane & 15);
        int s_l = (ee < ke) ? g_esrc[ee] : 0;
        float v = g_ssrc[s_l * HH + head] + sdst_h;
        v = (v > 0.f) ? v : 0.2f * v;
        float p_l = __expf(v);
        for (int e = 0; e < m; e++) {
            int s = __shfl_sync(0xffffffffu, s_l, e);
            float p0 = __shfl_sync(0xffffffffu, p_l, e);
            float p1 = __shfl_sync(0xffffffffu, p_l, 16 + e);
            z0 += p0; z1 += p1;
            uint2 r0 = *(const uint2*)(hb0 + (size_t)s * DD);
            uint2 r1 = *(const uint2*)(hb1 + (size_t)s * DD);
            float2 f00 = __half22float2(*(__half2*)&r0.x);
            float2 f01 = __half22float2(*(__half2*)&r0.y);
            float2 f10 = __half22float2(*(__half2*)&r1.x);
            float2 f11 = __half22float2(*(__half2*)&r1.y);
            a0.x += p0 * f00.x; a0.y += p0 * f00.y; a0.z += p0 * f01.x; a0.w += p0 * f01.y;
            a1.x += p1 * f10.x; a1.y += p1 * f10.y; a1.z += p1 * f11.x; a1.w += p1 * f11.y;
        }
    }

    float rz0 = 1.0f / z0, rz1 = 1.0f / z1;
    int col0 = 256 * w + lane * 4;
    float4 b0 = *(const float4*)(bias + col0);
    float4 b1 = *(const float4*)(bias + col0 + 128);
    __half2 o00 = __floats2half2_rn(a0.x * rz0 + b0.x, a0.y * rz0 + b0.y);
    __half2 o01 = __floats2half2_rn(a0.z * rz0 + b0.z, a0.w * rz0 + b0.w);
    __half2 o10 = __floats2half2_rn(a1.x * rz1 + b1.x, a1.y * rz1 + b1.y);
    __half2 o11 = __floats2half2_rn(a1.z * rz1 + b1.z, a1.w * rz1 + b1.w);
    *(uint2*)(out16 + (size_t)n * DD + col0) = make_uint2(*(uint32_t*)&o00, *(uint32_t*)&o01);
    *(uint2*)(out16 + (size_t)n * DD + col0 + 128) = make_uint2(*(uint32_t*)&o10, *(uint32_t*)&o11);
}

// ---------------- host orchestration ----------------
#define SMEM_BM128 ((2 * 128 * 40 + 2 * 128 * 40) * 2)   // 40960 B
#define SMEM_BM32  ((2 * 32 * 40 + 2 * 128 * 40) * 2)    // 25600 B

static void launch_small_h(const __half* A16, int widx, const float* bias, __half* Ch,
                           __half* wt) {
    dim3 grid(1, (NN + 31) / 32);
    k_gemm<32, true, true, true, false><<<grid, 256, SMEM_BM32>>>(
        A16, wt + widx * WSZ, bias, nullptr, nullptr, nullptr, Ch, NN, DD, CC);
}
static void launch_small_f(const __half* A16, int widx, const float* bias, float* Cf,
                           __half* wt) {
    dim3 grid(1, (NN + 31) / 32);
    k_gemm<32, true, true, false, false><<<grid, 256, SMEM_BM32>>>(
        A16, wt + widx * WSZ, bias, nullptr, nullptr, Cf, nullptr, NN, DD, CC);
}
static void launch_big(const __half* A16, int widx, __half* Ch,
                       const float* asrc, const float* adst, __half* wt) {
    dim3 grid(DD / 128, (NN + 127) / 128);
    k_gemm<128, false, false, true, true><<<grid, 256, SMEM_BM128>>>(
        A16, wt + widx * WSZ, nullptr, asrc, adst, nullptr, Ch, NN, CC, DD);
}

extern "C" void kernel_launch(void* const* d_in, const int* in_sizes, int n_in,
                              void* d_out, int out_size) {
    const float* x   = (const float*)d_in[0];
    const int*   ei  = (const int*)d_in[1];
    const float* w1  = (const float*)d_in[2];
    const float* as1 = (const float*)d_in[3];
    const float* ad1 = (const float*)d_in[4];
    const float* b1  = (const float*)d_in[5];
    const float* w2  = (const float*)d_in[6];
    const float* as2 = (const float*)d_in[7];
    const float* ad2 = (const float*)d_in[8];
    const float* b2  = (const float*)d_in[9];
    const float* w3  = (const float*)d_in[10];
    const float* as3 = (const float*)d_in[11];
    const float* ad3 = (const float*)d_in[12];
    const float* b3  = (const float*)d_in[13];
    const float* rw1 = (const float*)d_in[14];
    const float* rb1 = (const float*)d_in[15];
    const float* rw2 = (const float*)d_in[16];
    const float* rb2 = (const float*)d_in[17];
    const float* lw  = (const float*)d_in[18];
    const float* lb  = (const float*)d_in[19];
    float* out = (float*)d_out;

    __half *h16, *agg16, *feat16, *wt;
    cudaGetSymbolAddress((void**)&h16, g_h16);
    cudaGetSymbolAddress((void**)&agg16, g_agg16);
    cudaGetSymbolAddress((void**)&feat16, g_feat16);
    cudaGetSymbolAddress((void**)&wt, g_wt);

    cudaFuncSetAttribute((const void*)k_gemm<32, true, true, true, false>,
                         cudaFuncAttributeMaxDynamicSharedMemorySize, SMEM_BM32);
    cudaFuncSetAttribute((const void*)k_gemm<32, true, true, false, false>,
                         cudaFuncAttributeMaxDynamicSharedMemorySize, SMEM_BM32);
    cudaFuncSetAttribute((const void*)k_gemm<128, false, false, true, true>,
                         cudaFuncAttributeMaxDynamicSharedMemorySize, SMEM_BM128);

    // upfront: weights + CSR count (fused), scan, then fill + layer-1 (fused)
    k_cvt_count<<<(5 * WSZ + 255) / 256, 256>>>(rw1, w2, rw2, w3, lw, ei);
    k_scan<<<1, 1024>>>();
    k_fill_l1<<<665 + NN, 256>>>(ei, x, w1, as1, ad1, h16);

    // layer 1 aggregate
    k_aggregate<<<NN, 128>>>(h16, b1, agg16);

    // layer 2
    launch_small_h(agg16, 0, rb1, feat16, wt);
    launch_big(feat16, 1, h16, as2, ad2, wt);
    k_aggregate<<<NN, 128>>>(h16, b2, agg16);

    // layer 3
    launch_small_h(agg16, 2, rb2, feat16, wt);
    launch_big(feat16, 3, h16, as3, ad3, wt);
    k_aggregate<<<NN, 128>>>(h16, b3, agg16);

    // final projection
    launch_small_f(agg16, 4, lb, out, wt);
}

// round 16
// speedup vs baseline: 1.6895x; 1.0307x over previous
#include <cuda_runtime.h>
#include <cuda_fp16.h>
#include <math.h>
#include <stdint.h>

#define NN 10000
#define EE 160000
#define ETOT 170000   // EE + NN self loops
#define HH 8
#define CC 128
#define DD 1024
#define WSZ (DD * CC) // 131072 elements per weight matrix

// ---------------- scratch (static device memory; no allocations) ----------------
__device__ __half g_h16[NN * DD];     // fp16 per-layer h (gather + scores source)
__device__ __half g_agg16[NN * DD];   // fp16 aggregate output (feeds small GEMM)
__device__ __half g_feat16[NN * CC];  // fp16 feat (small GEMM out, big GEMM in)
__device__ float g_ssrc[NN * HH];
__device__ float g_sdst[NN * HH];
__device__ int   g_cnt[NN];           // BSS-zeroed; re-zeroed by k_scan each call
__device__ int   g_row[NN + 1];
__device__ int   g_cur[NN];
__device__ int   g_esrc[ETOT];        // src node per CSR position
__device__ __half g_wt[5 * WSZ];      // transposed fp16 weights [Nc,K]

__device__ __forceinline__ float gelu_exact(float x) {
    return x * normcdff(x);   // jax.nn.gelu(approximate=False)
}
__device__ __forceinline__ int edge_src(const int* ei, int e) {
    return (e < EE) ? ei[e] : (e - EE);
}
__device__ __forceinline__ int edge_dst(const int* ei, int e) {
    return (e < EE) ? ei[EE + e] : (e - EE);
}

// ---------------- fused: weight convert+transpose AND edge counting ----------------
__global__ void k_cvt_count(const float* __restrict__ w0, const float* __restrict__ w1_,
                            const float* __restrict__ w2_, const float* __restrict__ w3_,
                            const float* __restrict__ w4_, const int* __restrict__ ei) {
    int idx = blockIdx.x * 256 + threadIdx.x;
    if (idx < 5 * WSZ) {
        int which = idx / WSZ, r = idx - which * WSZ;
        const float* W;
        int K, Nc;
        switch (which) {
            case 0: W = w0;  K = 1024; Nc = 128;  break;
            case 1: W = w1_; K = 128;  Nc = 1024; break;
            case 2: W = w2_; K = 1024; Nc = 128;  break;
            case 3: W = w3_; K = 128;  Nc = 1024; break;
            default: W = w4_; K = 1024; Nc = 128; break;
        }
        int k = r / Nc, n = r - k * Nc;
        g_wt[which * WSZ + n * K + k] = __float2half_rn(W[r]);
    }
    if (idx < ETOT) atomicAdd(&g_cnt[edge_dst(ei, idx)], 1);
}

__global__ void k_scan() {
    __shared__ int sh[1024];
    int t = threadIdx.x;
    int base = t * 10;
    int cnt[10];
    int s = 0;
#pragma unroll
    for (int i = 0; i < 10; i++) {
        int j = base + i;
        cnt[i] = (j < NN) ? g_cnt[j] : 0;
        s += cnt[i];
        if (j < NN) g_cnt[j] = 0;
    }
    sh[t] = s;
    __syncthreads();
    for (int off = 1; off < 1024; off <<= 1) {
        int v = (t >= off) ? sh[t - off] : 0;
        __syncthreads();
        sh[t] += v;
        __syncthreads();
    }
    int run = sh[t] - s;
    for (int i = 0; i < 10; i++) {
        int j = base + i;
        if (j < NN) { g_row[j] = run; g_cur[j] = run; run += cnt[i]; }
    }
    if (t == 1023) g_row[NN] = sh[1023];
}

// ---------------- fused: CSR fill (blocks 0..664) + layer-1 h/scores (blocks 665..) ----------------
__global__ void __launch_bounds__(256) k_fill_l1(const int* __restrict__ ei,
                                                 const float* __restrict__ x,
                                                 const float* __restrict__ w1,
                                                 const float* __restrict__ asrc,
                                                 const float* __restrict__ adst,
                                                 __half* __restrict__ h16) {
    if (blockIdx.x < 665) {
        int e = blockIdx.x * 256 + threadIdx.x;
        if (e < ETOT) {
            int pos = atomicAdd(&g_cur[edge_dst(ei, e)], 1);
            g_esrc[pos] = edge_src(ei, e);
        }
        return;
    }
    int n = blockIdx.x - 665;
    int w = threadIdx.x >> 5, lane = threadIdx.x & 31;
    float4 xv = *(const float4*)(x + n * 4);
    int db = w * CC + lane * 4;
    float4 c0 = *(const float4*)(w1 + 0 * DD + db);
    float4 c1 = *(const float4*)(w1 + 1 * DD + db);
    float4 c2 = *(const float4*)(w1 + 2 * DD + db);
    float4 c3 = *(const float4*)(w1 + 3 * DD + db);
    float h0 = xv.x * c0.x + xv.y * c1.x + xv.z * c2.x + xv.w * c3.x;
    float h1 = xv.x * c0.y + xv.y * c1.y + xv.z * c2.y + xv.w * c3.y;
    float h2 = xv.x * c0.z + xv.y * c1.z + xv.z * c2.z + xv.w * c3.z;
    float h3 = xv.x * c0.w + xv.y * c1.w + xv.z * c2.w + xv.w * c3.w;
    __half2 p01 = __floats2half2_rn(h0, h1);
    __half2 p23 = __floats2half2_rn(h2, h3);
    *(uint2*)(h16 + (size_t)n * DD + db) =
        make_uint2(*(uint32_t*)&p01, *(uint32_t*)&p23);

    float4 a = *(const float4*)(asrc + db);
    float4 d = *(const float4*)(adst + db);
    float s1 = h0 * a.x + h1 * a.y + h2 * a.z + h3 * a.w;
    float s2 = h0 * d.x + h1 * d.y + h2 * d.z + h3 * d.w;
#pragma unroll
    for (int o = 16; o > 0; o >>= 1) {
        s1 += __shfl_xor_sync(0xffffffffu, s1, o);
        s2 += __shfl_xor_sync(0xffffffffu, s2, o);
    }
    if (lane == 0) {
        g_ssrc[n * HH + w] = s1;
        g_sdst[n * HH + w] = s2;
    }
}

// ---------------- fp16 GEMM, double-buffered smem ----------------
__device__ __forceinline__ void mma_f16(float* c, const uint32_t* a, const uint32_t* b) {
    asm volatile(
        "mma.sync.aligned.m16n8k16.row.col.f32.f16.f16.f32 "
        "{%0,%1,%2,%3}, {%4,%5,%6,%7}, {%8,%9}, {%0,%1,%2,%3};"
        : "+f"(c[0]), "+f"(c[1]), "+f"(c[2]), "+f"(c[3])
        : "r"(a[0]), "r"(a[1]), "r"(a[2]), "r"(a[3]), "r"(b[0]), "r"(b[1]));
}

template <int BM, bool GELU_A, bool ADD_BIAS, bool OUT_HALF, bool SCORES>
__global__ void __launch_bounds__(256) k_gemm(
    const __half* __restrict__ Ahg, const __half* __restrict__ Bg,
    const float* __restrict__ bias,
    const float* __restrict__ asrc, const float* __restrict__ adst,
    float* __restrict__ Cf, __half* __restrict__ Ch, int M, int K, int Nc) {
    constexpr int STR = 40;
    constexpr int WM = BM / 2;
    constexpr int MT = WM / 16;

    extern __shared__ __half dsm[];
    __half* AsB = dsm;
    __half* BsB = dsm + 2 * BM * STR;
    __shared__ float sa[128], sd[128];
    __shared__ float sSp[4][128], sDp[4][128];

    const int tid = threadIdx.x;
    const int wid = tid >> 5, lane = tid & 31;
    const int wm = wid & 1, wn = wid >> 1;
    const int gr = lane >> 2, tc = lane & 3;
    const int m0 = blockIdx.y * BM, n0 = blockIdx.x * 128;
    const int head = blockIdx.x;

    if (SCORES && tid < 128) {
        sa[tid] = asrc[head * 128 + tid];
        sd[tid] = adst[head * 128 + tid];
    }

    float acc[MT][4][4];
#pragma unroll
    for (int i = 0; i < MT; i++)
#pragma unroll
        for (int j = 0; j < 4; j++)
#pragma unroll
            for (int q = 0; q < 4; q++) acc[i][j][q] = 0.f;

    uint4 rAh128[2];
    uint2 rAh32;
    uint4 rB[2];
    const int ar128 = tid >> 1, aq128 = (tid & 1) * 2;
    const int ar32 = tid >> 3, aq32 = tid & 7;
    const int br_ = tid >> 1, bq_ = tid & 1;

    auto load_chunk = [&](int k0) {
        if (BM == 128) {
#pragma unroll
            for (int it = 0; it < 2; it++) {
                int q = aq128 + it;
                rAh128[it] = (m0 + ar128 < M)
                    ? *(const uint4*)(Ahg + (size_t)(m0 + ar128) * K + k0 + q * 8)
                    : make_uint4(0, 0, 0, 0);
            }
        } else {
            rAh32 = (m0 + ar32 < M)
                ? *(const uint2*)(Ahg + (size_t)(m0 + ar32) * K + k0 + aq32 * 4)
                : make_uint2(0, 0);
        }
#pragma unroll
        for (int it = 0; it < 2; it++) {
            int q = bq_ + it * 2;
            rB[it] = *(const uint4*)(Bg + (size_t)(n0 + br_) * K + k0 + q * 8);
        }
    };
    auto store_chunk = [&](int stage) {
        __half* As = AsB + stage * BM * STR;
        __half* Bs = BsB + stage * 128 * STR;
        if (BM == 128) {
#pragma unroll
            for (int it = 0; it < 2; it++) {
                int q = aq128 + it;
                *(uint4*)&As[ar128 * STR + q * 8] = rAh128[it];
            }
        } else {
            uint2 v = rAh32;
            if (GELU_A) {
                __half2 x01 = *(__half2*)&v.x;
                __half2 x23 = *(__half2*)&v.y;
                float2 f01 = __half22float2(x01);
                float2 f23 = __half22float2(x23);
                __half2 g01 = __floats2half2_rn(gelu_exact(f01.x), gelu_exact(f01.y));
                __half2 g23 = __floats2half2_rn(gelu_exact(f23.x), gelu_exact(f23.y));
                v = make_uint2(*(uint32_t*)&g01, *(uint32_t*)&g23);
            }
            *(uint2*)&As[ar32 * STR + aq32 * 4] = v;
        }
#pragma unroll
        for (int it = 0; it < 2; it++) {
            int q = bq_ + it * 2;
            *(uint4*)&Bs[br_ * STR + q * 8] = rB[it];
        }
    };

    const int nchunks = K >> 5;
    load_chunk(0);
    store_chunk(0);
    __syncthreads();

    for (int c = 0; c < nchunks; c++) {
        int b = c & 1;
        if (c + 1 < nchunks) load_chunk((c + 1) << 5);

        const __half* As = AsB + b * BM * STR;
        const __half* Bs = BsB + b * 128 * STR;
#pragma unroll
        for (int ks = 0; ks < 32; ks += 16) {
            uint32_t af[MT][4], bf[4][2];
#pragma unroll
            for (int i = 0; i < MT; i++) {
                int row = wm * WM + i * 16 + gr;
                int o = row * STR + ks + tc * 2;
                af[i][0] = *(const uint32_t*)&As[o];
                af[i][1] = *(const uint32_t*)&As[o + 8 * STR];
                af[i][2] = *(const uint32_t*)&As[o + 8];
                af[i][3] = *(const uint32_t*)&As[o + 8 * STR + 8];
            }
#pragma unroll
            for (int j = 0; j < 4; j++) {
                int nrow = wn * 32 + j * 8 + gr;
                int o = nrow * STR + ks + tc * 2;
                bf[j][0] = *(const uint32_t*)&Bs[o];
                bf[j][1] = *(const uint32_t*)&Bs[o + 8];
            }
#pragma unroll
            for (int i = 0; i < MT; i++)
#pragma unroll
                for (int j = 0; j < 4; j++)
                    mma_f16(acc[i][j], af[i], bf[j]);
        }
        if (c + 1 < nchunks) store_chunk(b ^ 1);
        __syncthreads();
    }

#pragma unroll
    for (int i = 0; i < MT; i++) {
        int row0 = m0 + wm * WM + i * 16 + gr;
#pragma unroll
        for (int j = 0; j < 4; j++) {
            int col = n0 + wn * 32 + j * 8 + tc * 2;
            float b0 = 0.f, b1 = 0.f;
            if (ADD_BIAS) { b0 = bias[col]; b1 = bias[col + 1]; }
            if (OUT_HALF) {
                __half2 v0 = __floats2half2_rn(acc[i][j][0] + b0, acc[i][j][1] + b1);
                __half2 v1 = __floats2half2_rn(acc[i][j][2] + b0, acc[i][j][3] + b1);
                if (row0 < M) *(uint32_t*)(Ch + (size_t)row0 * Nc + col) = *(uint32_t*)&v0;
                if (row0 + 8 < M) *(uint32_t*)(Ch + (size_t)(row0 + 8) * Nc + col) = *(uint32_t*)&v1;
            } else {
                if (row0 < M)
                    *(float2*)(Cf + (size_t)row0 * Nc + col) =
                        make_float2(acc[i][j][0] + b0, acc[i][j][1] + b1);
                if (row0 + 8 < M)
                    *(float2*)(Cf + (size_t)(row0 + 8) * Nc + col) =
                        make_float2(acc[i][j][2] + b0, acc[i][j][3] + b1);
            }
        }
    }

    if (SCORES) {
#pragma unroll
        for (int i = 0; i < MT; i++) {
            float p1a = 0.f, p1b = 0.f, p2a = 0.f, p2b = 0.f;
#pragma unroll
            for (int j = 0; j < 4; j++) {
                int col = wn * 32 + j * 8 + tc * 2;
                float a0 = sa[col], a1 = sa[col + 1];
                float d0 = sd[col], d1 = sd[col + 1];
                p1a += acc[i][j][0] * a0 + acc[i][j][1] * a1;
                p2a += acc[i][j][0] * d0 + acc[i][j][1] * d1;
                p1b += acc[i][j][2] * a0 + acc[i][j][3] * a1;
                p2b += acc[i][j][2] * d0 + acc[i][j][3] * d1;
            }
#pragma unroll
            for (int o = 1; o <= 2; o <<= 1) {
                p1a += __shfl_xor_sync(0xffffffffu, p1a, o);
                p1b += __shfl_xor_sync(0xffffffffu, p1b, o);
                p2a += __shfl_xor_sync(0xffffffffu, p2a, o);
                p2b += __shfl_xor_sync(0xffffffffu, p2b, o);
            }
            if (tc == 0) {
                int rl = wm * WM + i * 16 + gr;
                sSp[wn][rl] = p1a; sSp[wn][rl + 8] = p1b;
                sDp[wn][rl] = p2a; sDp[wn][rl + 8] = p2b;
            }
        }
        __syncthreads();
        if (tid < 128) {
            int row = m0 + tid;
            if (row < M) {
                float s1 = sSp[0][tid] + sSp[1][tid] + sSp[2][tid] + sSp[3][tid];
                float s2 = sDp[0][tid] + sDp[1][tid] + sDp[2][tid] + sDp[3][tid];
                g_ssrc[row * HH + head] = s1;
                g_sdst[row * HH + head] = s2;
            }
        }
    }
}

// ---------------- fused softmax + aggregation v5: one LDG.128 per lane per edge ----------------
// 128 threads / node. Warp w covers dims [256w, 256w+256); lane owns 8 contiguous
// halves. Lanes 0-15 belong to head 2w, lanes 16-31 to head 2w+1 (dim 128 boundary
// == lane 16 boundary). Per 16-edge batch lanes compute p once per (edge,head);
// consumed via one shfl selected by (lane&16). z needs no reduction (identical
// across lanes of a half-warp). No smem, no block barriers.
__global__ void __launch_bounds__(128) k_aggregate(const __half* __restrict__ h16,
                                                   const float* __restrict__ bias,
                                                   __half* __restrict__ out16) {
    int n = blockIdx.x;
    int w = threadIdx.x >> 5, lane = threadIdx.x & 31;
    int kb = g_row[n], ke = g_row[n + 1];
    int head = 2 * w + (lane >> 4);
    float sdst_h = g_sdst[n * HH + head];

    const __half* hb = h16 + 256 * w + lane * 8;   // 8 contiguous halves
    const int psel = lane & 16;

    float z = 0.f;
    float a0 = 0.f, a1 = 0.f, a2 = 0.f, a3 = 0.f;
    float a4 = 0.f, a5 = 0.f, a6 = 0.f, a7 = 0.f;

    for (int e0 = kb; e0 < ke; e0 += 16) {
        int m = min(16, ke - e0);
        int ee = e0 + (lane & 15);
        int s_l = (ee < ke) ? g_esrc[ee] : 0;
        float v = g_ssrc[s_l * HH + head] + sdst_h;
        v = (v > 0.f) ? v : 0.2f * v;
        float p_l = __expf(v);
        for (int e = 0; e < m; e++) {
            int s = __shfl_sync(0xffffffffu, s_l, e);
            float p = __shfl_sync(0xffffffffu, p_l, psel + e);
            z += p;
            uint4 r = *(const uint4*)(hb + (size_t)s * DD);
            float2 f0 = __half22float2(*(__half2*)&r.x);
            float2 f1 = __half22float2(*(__half2*)&r.y);
            float2 f2 = __half22float2(*(__half2*)&r.z);
            float2 f3 = __half22float2(*(__half2*)&r.w);
            a0 += p * f0.x; a1 += p * f0.y; a2 += p * f1.x; a3 += p * f1.y;
            a4 += p * f2.x; a5 += p * f2.y; a6 += p * f3.x; a7 += p * f3.y;
        }
    }

    float rz = 1.0f / z;
    int col = 256 * w + lane * 8;
    float4 b0 = *(const float4*)(bias + col);
    float4 b1 = *(const float4*)(bias + col + 4);
    __half2 o0 = __floats2half2_rn(a0 * rz + b0.x, a1 * rz + b0.y);
    __half2 o1 = __floats2half2_rn(a2 * rz + b0.z, a3 * rz + b0.w);
    __half2 o2 = __floats2half2_rn(a4 * rz + b1.x, a5 * rz + b1.y);
    __half2 o3 = __floats2half2_rn(a6 * rz + b1.z, a7 * rz + b1.w);
    *(uint4*)(out16 + (size_t)n * DD + col) =
        make_uint4(*(uint32_t*)&o0, *(uint32_t*)&o1, *(uint32_t*)&o2, *(uint32_t*)&o3);
}

// ---------------- host orchestration ----------------
#define SMEM_BM128 ((2 * 128 * 40 + 2 * 128 * 40) * 2)   // 40960 B
#define SMEM_BM32  ((2 * 32 * 40 + 2 * 128 * 40) * 2)    // 25600 B

static void launch_small_h(const __half* A16, int widx, const float* bias, __half* Ch,
                           __half* wt) {
    dim3 grid(1, (NN + 31) / 32);
    k_gemm<32, true, true, true, false><<<grid, 256, SMEM_BM32>>>(
        A16, wt + widx * WSZ, bias, nullptr, nullptr, nullptr, Ch, NN, DD, CC);
}
static void launch_small_f(const __half* A16, int widx, const float* bias, float* Cf,
                           __half* wt) {
    dim3 grid(1, (NN + 31) / 32);
    k_gemm<32, true, true, false, false><<<grid, 256, SMEM_BM32>>>(
        A16, wt + widx * WSZ, bias, nullptr, nullptr, Cf, nullptr, NN, DD, CC);
}
static void launch_big(const __half* A16, int widx, __half* Ch,
                       const float* asrc, const float* adst, __half* wt) {
    dim3 grid(DD / 128, (NN + 127) / 128);
    k_gemm<128, false, false, true, true><<<grid, 256, SMEM_BM128>>>(
        A16, wt + widx * WSZ, nullptr, asrc, adst, nullptr, Ch, NN, CC, DD);
}

extern "C" void kernel_launch(void* const* d_in, const int* in_sizes, int n_in,
                              void* d_out, int out_size) {
    const float* x   = (const float*)d_in[0];
    const int*   ei  = (const int*)d_in[1];
    const float* w1  = (const float*)d_in[2];
    const float* as1 = (const float*)d_in[3];
    const float* ad1 = (const float*)d_in[4];
    const float* b1  = (const float*)d_in[5];
    const float* w2  = (const float*)d_in[6];
    const float* as2 = (const float*)d_in[7];
    const float* ad2 = (const float*)d_in[8];
    const float* b2  = (const float*)d_in[9];
    const float* w3  = (const float*)d_in[10];
    const float* as3 = (const float*)d_in[11];
    const float* ad3 = (const float*)d_in[12];
    const float* b3  = (const float*)d_in[13];
    const float* rw1 = (const float*)d_in[14];
    const float* rb1 = (const float*)d_in[15];
    const float* rw2 = (const float*)d_in[16];
    const float* rb2 = (const float*)d_in[17];
    const float* lw  = (const float*)d_in[18];
    const float* lb  = (const float*)d_in[19];
    float* out = (float*)d_out;

    __half *h16, *agg16, *feat16, *wt;
    cudaGetSymbolAddress((void**)&h16, g_h16);
    cudaGetSymbolAddress((void**)&agg16, g_agg16);
    cudaGetSymbolAddress((void**)&feat16, g_feat16);
    cudaGetSymbolAddress((void**)&wt, g_wt);

    cudaFuncSetAttribute((const void*)k_gemm<32, true, true, true, false>,
                         cudaFuncAttributeMaxDynamicSharedMemorySize, SMEM_BM32);
    cudaFuncSetAttribute((const void*)k_gemm<32, true, true, false, false>,
                         cudaFuncAttributeMaxDynamicSharedMemorySize, SMEM_BM32);
    cudaFuncSetAttribute((const void*)k_gemm<128, false, false, true, true>,
                         cudaFuncAttributeMaxDynamicSharedMemorySize, SMEM_BM128);

    // upfront: weights + CSR count (fused), scan, then fill + layer-1 (fused)
    k_cvt_count<<<(5 * WSZ + 255) / 256, 256>>>(rw1, w2, rw2, w3, lw, ei);
    k_scan<<<1, 1024>>>();
    k_fill_l1<<<665 + NN, 256>>>(ei, x, w1, as1, ad1, h16);

    // layer 1 aggregate
    k_aggregate<<<NN, 128>>>(h16, b1, agg16);

    // layer 2
    launch_small_h(agg16, 0, rb1, feat16, wt);
    launch_big(feat16, 1, h16, as2, ad2, wt);
    k_aggregate<<<NN, 128>>>(h16, b2, agg16);

    // layer 3
    launch_small_h(agg16, 2, rb2, feat16, wt);
    launch_big(feat16, 3, h16, as3, ad3, wt);
    k_aggregate<<<NN, 128>>>(h16, b3, agg16);

    // final projection
    launch_small_f(agg16, 4, lb, out, wt);
}